// round 1
// baseline (speedup 1.0000x reference)
#include <cuda_runtime.h>
#include <math.h>

#define NB 128
#define NQ 30
#define ND 256
#define NE 300
#define NC 128

// ---------------- scratch (device globals; no allocation allowed) ----------------
__device__ float g_WT[230400];                 // per-gram transposed weights [k][c]
__device__ float g_Q[NB * NQ * 384];           // normalized query conv outputs [b][q][g*128+c]
__device__ float g_D[NB * ND * 384];           // normalized doc conv outputs
__device__ float g_feat[NB * 99];              // pooled features

// ---------------- weight transpose/stack ----------------
// WT layout per gram g (K_g = 300*(g+1)): WT_g[k][c], k = tap*300 + e, c = out channel
// offsets (floats): g0: 0, g1: 38400, g2: 115200
__global__ __launch_bounds__(256) void prep_wt(const float* __restrict__ w1,
                                               const float* __restrict__ w2,
                                               const float* __restrict__ w3)
{
    int idx = blockIdx.x * 256 + threadIdx.x;
    if (idx >= 230400) return;
    int g, off;
    if (idx < 38400)       { g = 0; off = idx; }
    else if (idx < 115200) { g = 1; off = idx - 38400; }
    else                   { g = 2; off = idx - 115200; }
    int k = off >> 7;        // /128
    int c = off & 127;
    int tap = k / 300;
    int e = k - tap * 300;
    const float* w = (g == 0) ? w1 : ((g == 1) ? w2 : w3);
    // conv_w{g+1} layout: [128][300][g+1]
    g_WT[idx] = w[(c * 300 + e) * (g + 1) + tap];
}

// ---------------- conv + bias + relu + rowwise L2 normalize ----------------
// GEMM: [L positions] x [K_g] @ [K_g x 128] per (batch, gram). im2col on the fly.
// Tile: M=64 positions, N=128 channels, Ks=16. 256 threads: ty in [0,16) -> 4 pos, tx in [0,16) -> 8 ch.
template<int L, bool IS_Q>
__global__ __launch_bounds__(256) void conv_kernel(const float* __restrict__ X,
                                                   const float* __restrict__ bs0,
                                                   const float* __restrict__ bs1,
                                                   const float* __restrict__ bs2)
{
    __shared__ float As[64 * 16];
    __shared__ float Bs[16 * 128];

    const int g  = blockIdx.z;
    const int b  = blockIdx.y;
    const int p0 = blockIdx.x * 64;
    const int K  = 300 * (g + 1);
    const float* WT   = g_WT + ((g == 0) ? 0 : ((g == 1) ? 38400 : 115200));
    const float* bias = (g == 0) ? bs0 : ((g == 1) ? bs1 : bs2);
    float* OUT = IS_Q ? g_Q : g_D;

    const int tid = threadIdx.x;
    const int ty = tid >> 4;
    const int tx = tid & 15;

    float acc[4][8];
#pragma unroll
    for (int i = 0; i < 4; i++)
#pragma unroll
        for (int j = 0; j < 8; j++) acc[i][j] = 0.f;

    const float* Xb = X + (size_t)b * L * NE;

    for (int ks = 0; ks < K; ks += 16) {
        // --- load A tile (im2col, zero-padded) : 64x16, 4 consecutive kk per thread ---
        {
            int base = tid * 4;
            int p   = base >> 4;
            int kk0 = base & 15;
            float t0 = 0.f, t1 = 0.f, t2 = 0.f, t3 = 0.f;
#pragma unroll
            for (int u = 0; u < 4; u++) {
                int k = ks + kk0 + u;
                float v = 0.f;
                if (k < K) {
                    int tap = k / 300;
                    int e = k - tap * 300;
                    int pos = p0 + p + tap;
                    if (pos < L) v = Xb[pos * NE + e];
                }
                if (u == 0) t0 = v; else if (u == 1) t1 = v; else if (u == 2) t2 = v; else t3 = v;
            }
            *(float4*)&As[p * 16 + kk0] = make_float4(t0, t1, t2, t3);
        }
        // --- load B tile: 16x128, two float4 per thread ---
#pragma unroll
        for (int v2 = 0; v2 < 2; v2++) {
            int idx4 = tid * 2 + v2;
            int off = idx4 * 4;
            int kk = off >> 7;
            int cc = off & 127;
            int k = ks + kk;
            float4 bv = make_float4(0.f, 0.f, 0.f, 0.f);
            if (k < K) bv = *(const float4*)&WT[k * 128 + cc];
            *(float4*)&Bs[kk * 128 + cc] = bv;
        }
        __syncthreads();
#pragma unroll
        for (int kk = 0; kk < 16; kk++) {
            float a0 = As[(ty * 4 + 0) * 16 + kk];
            float a1 = As[(ty * 4 + 1) * 16 + kk];
            float a2 = As[(ty * 4 + 2) * 16 + kk];
            float a3 = As[(ty * 4 + 3) * 16 + kk];
            float4 bA = *(float4*)&Bs[kk * 128 + tx * 8];
            float4 bB = *(float4*)&Bs[kk * 128 + tx * 8 + 4];
            float bb[8] = {bA.x, bA.y, bA.z, bA.w, bB.x, bB.y, bB.z, bB.w};
#pragma unroll
            for (int j = 0; j < 8; j++) {
                acc[0][j] += a0 * bb[j];
                acc[1][j] += a1 * bb[j];
                acc[2][j] += a2 * bb[j];
                acc[3][j] += a3 * bb[j];
            }
        }
        __syncthreads();
    }

    // epilogue: bias + relu + per-position L2 norm over the 128 gram channels
    float4 bv0 = *(const float4*)&bias[tx * 8];
    float4 bv1 = *(const float4*)&bias[tx * 8 + 4];
    float bb[8] = {bv0.x, bv0.y, bv0.z, bv0.w, bv1.x, bv1.y, bv1.z, bv1.w};
#pragma unroll
    for (int i = 0; i < 4; i++) {
        float v[8];
        float ssq = 0.f;
#pragma unroll
        for (int j = 0; j < 8; j++) {
            float t = acc[i][j] + bb[j];
            t = fmaxf(t, 0.f);
            v[j] = t;
            ssq += t * t;
        }
        // reduce over the 16 tx lanes sharing this ty (lanes differ only in bits 0..3)
        ssq += __shfl_xor_sync(0xffffffffu, ssq, 1);
        ssq += __shfl_xor_sync(0xffffffffu, ssq, 2);
        ssq += __shfl_xor_sync(0xffffffffu, ssq, 4);
        ssq += __shfl_xor_sync(0xffffffffu, ssq, 8);
        float inv = 1.f / (sqrtf(ssq) + 1e-13f);
        int p = p0 + ty * 4 + i;
        if (p < L) {
            float* o = OUT + ((size_t)(b * L + p)) * 384 + g * 128 + tx * 8;
            *(float4*)&o[0] = make_float4(v[0] * inv, v[1] * inv, v[2] * inv, v[3] * inv);
            *(float4*)&o[4] = make_float4(v[4] * inv, v[5] * inv, v[6] * inv, v[7] * inv);
        }
    }
}

// ---------------- kernel pooling ----------------
// One block per (batch, gram-pair). smem-resident qn [32x128] (rows 30,31 zero) and dn [256x129 padded].
// Thread (qq=tid/32, dd=tid%32): 4 q-rows x 8 d-cols micro-tile. RBF via 2-exp factorization
// (valid because ReLU => cos in [0,1]).
__global__ __launch_bounds__(256) void pool_kernel(const float* __restrict__ qmask,
                                                   const float* __restrict__ dmask)
{
    extern __shared__ float sm[];
    float* ds   = sm;                 // 256*129
    float* qs   = sm + 256 * 129;     // 32*128
    float* qm   = qs + 32 * 128;      // 32
    float* dm   = qm + 32;            // 256
    float* wred = dm + 256;           // 8*11

    const int b    = blockIdx.x;
    const int pair = blockIdx.y;
    const int gi = pair / 3;
    const int gt = pair - gi * 3;
    const int tid = threadIdx.x;

    const float* Db = g_D + ((size_t)b * ND) * 384 + gt * 128;
    const float* Qb = g_Q + ((size_t)b * NQ) * 384 + gi * 128;

    // load doc tile (256x128 -> stride-129 smem)
#pragma unroll 4
    for (int it = 0; it < 32; it++) {
        int idx4 = tid + it * 256;
        int d  = idx4 >> 5;
        int c4 = (idx4 & 31) * 4;
        float4 v = *(const float4*)&Db[(size_t)d * 384 + c4];
        float* dst = &ds[d * 129 + c4];
        dst[0] = v.x; dst[1] = v.y; dst[2] = v.z; dst[3] = v.w;
    }
    // load query tile (rows >= 30 zeroed)
#pragma unroll
    for (int it = 0; it < 16; it++) {
        int idx = tid + it * 256;
        int q = idx >> 7;
        int c = idx & 127;
        qs[idx] = (q < NQ) ? Qb[q * 384 + c] : 0.f;
    }
    if (tid < 32)  qm[tid] = (tid < NQ) ? qmask[b * NQ + tid] : 0.f;
    dm[tid] = (tid < 256) ? dmask[b * ND + tid] : 0.f;
    __syncthreads();

    const int qq = tid >> 5;
    const int dd = tid & 31;

    float cosv[4][8];
#pragma unroll
    for (int i = 0; i < 4; i++)
#pragma unroll
        for (int ii = 0; ii < 8; ii++) cosv[i][ii] = 0.f;

#pragma unroll 2
    for (int k = 0; k < 128; k++) {
        float qv0 = qs[(qq * 4 + 0) * 128 + k];
        float qv1 = qs[(qq * 4 + 1) * 128 + k];
        float qv2 = qs[(qq * 4 + 2) * 128 + k];
        float qv3 = qs[(qq * 4 + 3) * 128 + k];
#pragma unroll
        for (int ii = 0; ii < 8; ii++) {
            float dv = ds[(dd + 32 * ii) * 129 + k];
            cosv[0][ii] += qv0 * dv;
            cosv[1][ii] += qv1 * dv;
            cosv[2][ii] += qv2 * dv;
            cosv[3][ii] += qv3 * dv;
        }
    }

    // RBF kernels. mu_j = 0.9 - 0.2(j-1) (j=1..10, sigma=0.1): v_j = e1 * t^(j-1) * u^((j-1)^2),
    // e1 = exp(-50 x^2), t = exp(-20 x), x = c - 0.9, u = e^-2.  Kernel 0: mu=1, sigma=0.001.
    float qacc[4][11];
#pragma unroll
    for (int i = 0; i < 4; i++)
#pragma unroll
        for (int kk2 = 0; kk2 < 11; kk2++) qacc[i][kk2] = 0.f;

    const float U1 = 0.13533528323661270f;   // e^-2
    const float U2 = 0.018315638888734179f;  // e^-4
#pragma unroll
    for (int i = 0; i < 4; i++) {
        float qmv = qm[qq * 4 + i];
#pragma unroll
        for (int ii = 0; ii < 8; ii++) {
            int d = dd + 32 * ii;
            float m = qmv * dm[d];
            float c = cosv[i][ii] * m;
            float x = c - 0.9f;
            float e1 = __expf(-50.f * x * x) * m;
            float t  = __expf(-20.f * x);
            float t0 = c - 1.0f;
            qacc[i][0] += __expf(-500000.f * t0 * t0) * m;
            float v = e1;
            qacc[i][1] += v;
            float r = t * U1;
#pragma unroll
            for (int j = 2; j < 11; j++) {
                v *= r;
                qacc[i][j] += v;
                r *= U2;
            }
        }
    }

    // reduce the per-(q,kernel) sums across the 32 dd-lanes (full warp)
#pragma unroll
    for (int i = 0; i < 4; i++)
#pragma unroll
        for (int kk2 = 0; kk2 < 11; kk2++) {
            float v = qacc[i][kk2];
            v += __shfl_xor_sync(0xffffffffu, v, 16);
            v += __shfl_xor_sync(0xffffffffu, v, 8);
            v += __shfl_xor_sync(0xffffffffu, v, 4);
            v += __shfl_xor_sync(0xffffffffu, v, 2);
            v += __shfl_xor_sync(0xffffffffu, v, 1);
            qacc[i][kk2] = v;
        }

    if (dd == 0) {
        float part[11];
#pragma unroll
        for (int kk2 = 0; kk2 < 11; kk2++) part[kk2] = 0.f;
#pragma unroll
        for (int i = 0; i < 4; i++) {
            float qmv = qm[qq * 4 + i] * 0.01f;
#pragma unroll
            for (int kk2 = 0; kk2 < 11; kk2++) {
                float pk = fmaxf(qacc[i][kk2], 1e-10f);
                part[kk2] += __logf(pk) * qmv;
            }
        }
#pragma unroll
        for (int kk2 = 0; kk2 < 11; kk2++) wred[qq * 11 + kk2] = part[kk2];
    }
    __syncthreads();
    if (tid < 11) {
        float s = 0.f;
#pragma unroll
        for (int w = 0; w < 8; w++) s += wred[w * 11 + tid];
        g_feat[b * 99 + pair * 11 + tid] = s;
    }
}

// ---------------- final dense ----------------
__global__ void final_kernel(const float* __restrict__ dw, float* __restrict__ out)
{
    int b = threadIdx.x;
    if (b < NB) {
        float s = 0.f;
#pragma unroll
        for (int j = 0; j < 99; j++) s += g_feat[b * 99 + j] * dw[j];
        out[b] = s;
    }
}

// ---------------- launch ----------------
extern "C" void kernel_launch(void* const* d_in, const int* in_sizes, int n_in,
                              void* d_out, int out_size)
{
    const float* qe    = (const float*)d_in[0];
    const float* de    = (const float*)d_in[1];
    const float* qmask = (const float*)d_in[2];
    const float* dmask = (const float*)d_in[3];
    const float* w1    = (const float*)d_in[4];
    const float* b1    = (const float*)d_in[5];
    const float* w2    = (const float*)d_in[6];
    const float* b2    = (const float*)d_in[7];
    const float* w3    = (const float*)d_in[8];
    const float* b3    = (const float*)d_in[9];
    const float* dw    = (const float*)d_in[10];
    float* out = (float*)d_out;

    prep_wt<<<(230400 + 255) / 256, 256>>>(w1, w2, w3);
    conv_kernel<NQ, true ><<<dim3(1, NB, 3), 256>>>(qe, b1, b2, b3);
    conv_kernel<ND, false><<<dim3(4, NB, 3), 256>>>(de, b1, b2, b3);

    int smem = (256 * 129 + 32 * 128 + 32 + 256 + 88) * (int)sizeof(float);
    cudaFuncSetAttribute(pool_kernel, cudaFuncAttributeMaxDynamicSharedMemorySize, smem);
    pool_kernel<<<dim3(NB, 9), 256, smem>>>(qmask, dmask);

    final_kernel<<<1, 128>>>(dw, out);
}